// round 5
// baseline (speedup 1.0000x reference)
#include <cuda_runtime.h>
#include <math.h>

// Problem constants (fixed by the dataset)
#define NSEG 8192
#define HDIM 1024
#define BM 128
#define BN 128
#define BK 8
#define BMP 132   // 128 + 4 pad: conflict-free transposed stores, 16B-aligned rows
#define NTILE (HDIM / BN)   // 8 column-tiles

// Scratch (no cudaMalloc allowed): 32 MB group means + partials + bounds
__device__ float g_h[(size_t)NSEG * HDIM];
__device__ float g_partial[NSEG * NTILE];
__device__ int   g_start[NSEG + 1];

// ---------------------------------------------------------------------------
// Kernel 0: segment boundaries. segment_ids is sorted ascending, so
// start[g] = lower_bound(seg, g). Range for group g is [start[g], start[g+1]).
// ---------------------------------------------------------------------------
__global__ void seg_bounds_kernel(const int* __restrict__ seg, int n) {
    int g = blockIdx.x * blockDim.x + threadIdx.x;
    if (g > NSEG) return;
    int lo = 0, hi = n;
    while (lo < hi) {
        int mid = (lo + hi) >> 1;
        if (seg[mid] < g) lo = mid + 1; else hi = mid;
    }
    g_start[g] = lo;
}

// ---------------------------------------------------------------------------
// Kernel 1: gather + per-group mean. One block per group, 256 threads,
// each thread owns 4 contiguous columns (float4). Fixed-order accumulation
// -> deterministic. Rows are 4KB and fully coalesced per row.
// ---------------------------------------------------------------------------
__global__ __launch_bounds__(256) void seg_mean_kernel(
    const float* __restrict__ hid, const int* __restrict__ idx) {
    int g = blockIdx.x;
    int t = threadIdx.x;
    int s = g_start[g];
    int e = g_start[g + 1];
    float4 acc = make_float4(0.f, 0.f, 0.f, 0.f);
    const float4* h4 = (const float4*)hid;
    int i = s;
    // 2-deep software pipeline for a little MLP on the row loads
    for (; i + 1 < e; i += 2) {
        int r0 = __ldg(&idx[i]);
        int r1 = __ldg(&idx[i + 1]);
        float4 v0 = h4[(size_t)r0 * (HDIM / 4) + t];
        float4 v1 = h4[(size_t)r1 * (HDIM / 4) + t];
        acc.x += v0.x; acc.y += v0.y; acc.z += v0.z; acc.w += v0.w;
        acc.x += v1.x; acc.y += v1.y; acc.z += v1.z; acc.w += v1.w;
    }
    if (i < e) {
        int r = __ldg(&idx[i]);
        float4 v = h4[(size_t)r * (HDIM / 4) + t];
        acc.x += v.x; acc.y += v.y; acc.z += v.z; acc.w += v.w;
    }
    float inv = 1.0f / fmaxf((float)(e - s), 1.0f);
    acc.x *= inv; acc.y *= inv; acc.z *= inv; acc.w *= inv;
    ((float4*)g_h)[(size_t)g * (HDIM / 4) + t] = acc;
}

// ---------------------------------------------------------------------------
// Kernel 2: fused SGEMM (z = h @ W^T + b) + exact-erf GELU + projection.
// 128x128 tile per block, BK=8, 256 threads, 8x8 register micro-tiles,
// double-buffered smem (one __syncthreads per K-slab, next-slab gmem loads
// overlapped into registers during compute).
// Epilogue: gelu(z)*W_proj[n], reduce this block's 128 columns per row,
// one partial per (row, n-tile). No atomics -> deterministic.
// ---------------------------------------------------------------------------
__global__ __launch_bounds__(256) void gemm_gelu_proj_kernel(
    const float* __restrict__ W, const float* __restrict__ bd,
    const float* __restrict__ Wp) {
    __shared__ __align__(16) float As[2][BK][BMP];
    __shared__ __align__(16) float Bs[2][BK][BMP];

    int tid = threadIdx.x;
    int tx = tid & 15;        // column group (8 cols each)
    int ty = tid >> 4;        // row group (8 rows each)
    int bn = blockIdx.x;      // 0..7
    int bm = blockIdx.y;      // 0..63

    int lr = tid >> 1;        // load row within tile: 0..127
    int lk = (tid & 1) << 2;  // load k offset: 0 or 4

    const float* Aptr = g_h + (size_t)(bm * BM + lr) * HDIM + lk;
    const float* Bptr = W   + (size_t)(bn * BN + lr) * HDIM + lk;

    float acc[8][8];
#pragma unroll
    for (int i = 0; i < 8; i++)
#pragma unroll
        for (int j = 0; j < 8; j++) acc[i][j] = 0.f;

    // Prologue: load slab 0
    {
        float4 av = *(const float4*)Aptr;
        float4 bv = *(const float4*)Bptr;
        As[0][lk + 0][lr] = av.x; As[0][lk + 1][lr] = av.y;
        As[0][lk + 2][lr] = av.z; As[0][lk + 3][lr] = av.w;
        Bs[0][lk + 0][lr] = bv.x; Bs[0][lk + 1][lr] = bv.y;
        Bs[0][lk + 2][lr] = bv.z; Bs[0][lk + 3][lr] = bv.w;
    }
    __syncthreads();

    int buf = 0;
    for (int k0 = 0; k0 < HDIM; k0 += BK) {
        float4 av, bv;
        bool more = (k0 + BK < HDIM);
        if (more) {
            av = *(const float4*)(Aptr + k0 + BK);
            bv = *(const float4*)(Bptr + k0 + BK);
        }
#pragma unroll
        for (int k = 0; k < BK; k++) {
            float4 a0 = *(const float4*)&As[buf][k][ty * 8];
            float4 a1 = *(const float4*)&As[buf][k][ty * 8 + 4];
            float4 b0 = *(const float4*)&Bs[buf][k][tx * 8];
            float4 b1 = *(const float4*)&Bs[buf][k][tx * 8 + 4];
            float a[8] = {a0.x, a0.y, a0.z, a0.w, a1.x, a1.y, a1.z, a1.w};
            float b[8] = {b0.x, b0.y, b0.z, b0.w, b1.x, b1.y, b1.z, b1.w};
#pragma unroll
            for (int i = 0; i < 8; i++)
#pragma unroll
                for (int j = 0; j < 8; j++)
                    acc[i][j] += a[i] * b[j];
        }
        if (more) {
            int nb = buf ^ 1;
            As[nb][lk + 0][lr] = av.x; As[nb][lk + 1][lr] = av.y;
            As[nb][lk + 2][lr] = av.z; As[nb][lk + 3][lr] = av.w;
            Bs[nb][lk + 0][lr] = bv.x; Bs[nb][lk + 1][lr] = bv.y;
            Bs[nb][lk + 2][lr] = bv.z; Bs[nb][lk + 3][lr] = bv.w;
            __syncthreads();
            buf = nb;
        }
    }

    // Epilogue: bias + exact GELU + projection weight, reduce over this
    // block's 128 columns for each of its 128 rows.
    float rsum[8] = {0.f, 0.f, 0.f, 0.f, 0.f, 0.f, 0.f, 0.f};
#pragma unroll
    for (int j = 0; j < 8; j++) {
        int n = bn * BN + tx * 8 + j;
        float bdn = __ldg(&bd[n]);
        float wpn = __ldg(&Wp[n]);
#pragma unroll
        for (int i = 0; i < 8; i++) {
            float x = acc[i][j] + bdn;
            float ge = 0.5f * x * (1.0f + erff(x * 0.70710678118654752f));
            rsum[i] += ge * wpn;
        }
    }

    __syncthreads();          // last compute slab read smem above; now reuse it
    float* red = &As[0][0][0];  // 128*16 = 2048 floats needed, 2112 available
#pragma unroll
    for (int i = 0; i < 8; i++)
        red[(ty * 8 + i) * 16 + tx] = rsum[i];
    __syncthreads();

    if (tid < BM) {
        float s = 0.f;
#pragma unroll
        for (int j = 0; j < 16; j++) s += red[tid * 16 + j];
        g_partial[(bm * BM + tid) * NTILE + bn] = s;
    }
}

// ---------------------------------------------------------------------------
// Kernel 3: sum the NTILE column-tile partials per row, add b_proj.
// ---------------------------------------------------------------------------
__global__ void finalize_kernel(float* __restrict__ out,
                                const float* __restrict__ bp) {
    int g = blockIdx.x * blockDim.x + threadIdx.x;
    if (g >= NSEG) return;
    float s = bp[0];
#pragma unroll
    for (int j = 0; j < NTILE; j++) s += g_partial[g * NTILE + j];
    out[g] = s;
}

extern "C" void kernel_launch(void* const* d_in, const int* in_sizes, int n_in,
                              void* d_out, int out_size) {
    const float* hid     = (const float*)d_in[0];  // [B*S, H] = [32768, 1024]
    const int*   indices = (const int*)d_in[1];    // [65536]
    const int*   seg     = (const int*)d_in[2];    // [65536] sorted
    const float* W       = (const float*)d_in[3];  // [1024, 1024]
    const float* bd      = (const float*)d_in[4];  // [1024]
    const float* Wp      = (const float*)d_in[5];  // [1, 1024]
    const float* bp      = (const float*)d_in[6];  // [1]
    float* out = (float*)d_out;                    // [8192]
    int n_idx = in_sizes[1];

    seg_bounds_kernel<<<(NSEG + 1 + 255) / 256, 256>>>(seg, n_idx);
    seg_mean_kernel<<<NSEG, 256>>>(hid, indices);
    gemm_gelu_proj_kernel<<<dim3(HDIM / BN, NSEG / BM), 256>>>(W, bd, Wp);
    finalize_kernel<<<NSEG / 256, 256>>>(out, bp);
}